// round 2
// baseline (speedup 1.0000x reference)
#include <cuda_runtime.h>
#include <math.h>
#include <stdint.h>

// Problem constants
#define B_   2
#define T_   2048
#define C_   1024
#define H_   16
#define KD_  64
#define VD_  128
#define VBD_ 2048
#define M_   (B_ * T_)   // 4096 rows

// ---------------------------------------------------------------------------
// Scratch (static device globals -- no allocation allowed)
// ---------------------------------------------------------------------------
__device__ float g_qk[(size_t)M_ * 2048];   // [B*T, 2C]  q | k
__device__ float g_v [(size_t)M_ * 2048];   // [B*T, VBD]
__device__ float g_g [(size_t)M_ * 2048];   // [B*T, VBD] gate
__device__ float g_y [(size_t)M_ * 2048];   // [B*T, VBD] gated normalized attn out

// ---------------------------------------------------------------------------
// SGEMM: C = A @ B + bias.  A [M,K] rm, B [K,N] rm, C [M,N] rm.
// 128x128 block, BK=8, 256 threads, 8x8 per-thread microtile.
// All dims are multiples of the tile sizes (4096 x {1024,2048} x {1024,2048}).
// ---------------------------------------------------------------------------
template<int BM, int BN, int BK, int TM, int TN>
__global__ void __launch_bounds__(256)
sgemm_bias(const float* __restrict__ A, const float* __restrict__ Bm,
           const float* __restrict__ bias, float* __restrict__ Cm,
           int M, int N, int K)
{
    __shared__ float As[BK][BM];   // transposed A tile
    __shared__ float Bs[BK][BN];

    const int tid = threadIdx.x;
    const int ty  = tid >> 4;      // 0..15
    const int tx  = tid & 15;      // 0..15

    const int rowBase = blockIdx.y * BM;
    const int colBase = blockIdx.x * BN;

    const float* Ab = A  + (size_t)rowBase * K;
    const float* Bb = Bm + colBase;

    // A tile load mapping: 128 rows x 8 cols = 256 float4
    const int aRow = tid >> 1;
    const int aCol = (tid & 1) * 4;
    // B tile load mapping: 8 rows x 128 cols = 256 float4
    const int bRow = tid >> 5;
    const int bCol = (tid & 31) * 4;

    float acc[TM][TN];
#pragma unroll
    for (int i = 0; i < TM; i++)
#pragma unroll
        for (int j = 0; j < TN; j++) acc[i][j] = 0.f;

    for (int k0 = 0; k0 < K; k0 += BK) {
        float4 a4 = *(const float4*)(Ab + (size_t)aRow * K + k0 + aCol);
        As[aCol + 0][aRow] = a4.x;
        As[aCol + 1][aRow] = a4.y;
        As[aCol + 2][aRow] = a4.z;
        As[aCol + 3][aRow] = a4.w;
        float4 b4 = *(const float4*)(Bb + (size_t)(k0 + bRow) * N + bCol);
        *(float4*)(&Bs[bRow][bCol]) = b4;
        __syncthreads();

#pragma unroll
        for (int k = 0; k < BK; k++) {
            float ra[TM], rb[TN];
#pragma unroll
            for (int i = 0; i < TM; i += 4)
                *(float4*)&ra[i] = *(const float4*)&As[k][ty * TM + i];
#pragma unroll
            for (int j = 0; j < TN; j += 4)
                *(float4*)&rb[j] = *(const float4*)&Bs[k][tx * TN + j];
#pragma unroll
            for (int i = 0; i < TM; i++)
#pragma unroll
                for (int j = 0; j < TN; j++)
                    acc[i][j] = fmaf(ra[i], rb[j], acc[i][j]);
        }
        __syncthreads();
    }

#pragma unroll
    for (int i = 0; i < TM; i++) {
        const int r = rowBase + ty * TM + i;
#pragma unroll
        for (int j = 0; j < TN; j += 4) {
            const int c = colBase + tx * TN + j;
            float4 o;
            o.x = acc[i][j + 0] + __ldg(&bias[c + 0]);
            o.y = acc[i][j + 1] + __ldg(&bias[c + 1]);
            o.z = acc[i][j + 2] + __ldg(&bias[c + 2]);
            o.w = acc[i][j + 3] + __ldg(&bias[c + 3]);
            *(float4*)(Cm + (size_t)r * N + c) = o;
        }
    }
}

// ---------------------------------------------------------------------------
// Retention attention core, fused with RMSNorm + gating.
// grid = (T/64, H, B), 256 threads.
// Streams causal key tiles; accumulates O = S@V and rowAbs = sum |S| without
// materializing the score matrix (denominator is linear in S -> exact).
// S = (q.k) * exp(g*ri) * exp(g*(t0-s0-cj)) * rsqrt(expm1(g*(t+1))/expm1(g))
// Epilogue: O /= clamp(rowAbs,1,5e4); RMSNorm over VD=128; multiply by gate.
// Reads q/k from g_qk, v from g_v, gate from g_g; writes g_y.
// ---------------------------------------------------------------------------
#define BQ  64
#define BKT 64
// smem floats: Qt 64*64, Kt 64*64, Ss 64*65, Vs 64*128
#define ATT_SMEM_FLOATS (64*64 + 64*64 + 64*65 + 64*128)
#define ATT_SMEM_BYTES  (ATT_SMEM_FLOATS * 4)

__global__ void __launch_bounds__(256)
retention_attn()
{
    extern __shared__ float sm[];
    float* Qt = sm;                    // [k][r]  64x64 transposed
    float* Kt = Qt + 64 * 64;          // [k][s]  64x64 transposed
    float* Ss = Kt + 64 * 64;          // [r][c]  64x65 (padded)
    float* Vs = Ss + 64 * 65;          // [s][v]  64x128

    const float* qk = g_qk;
    const float* vb = g_v;
    const float* gb = g_g;
    float*       yb = g_y;

    const int tid = threadIdx.x;
    const int ty  = tid >> 4;          // 0..15
    const int tx  = tid & 15;          // 0..15
    const int r0  = ty * 4;            // query rows owned (4)
    const int c0  = tx * 4;            // score cols owned (4)

    const int qi = blockIdx.x;
    const int h  = blockIdx.y;
    const int b  = blockIdx.z;
    const int t0 = qi * BQ;

    const float gamma = log1pf(-exp2f(-5.0f - (float)h));
    const float em1g  = expm1f(gamma);

    // Load Q tile transposed
    {
        const int row = tid >> 2;
        const int cb  = (tid & 3) * 16;
        const float* qp = qk + ((size_t)(b * T_ + t0 + row)) * (2 * C_) + (size_t)h * KD_ + cb;
#pragma unroll
        for (int it = 0; it < 4; it++) {
            float4 v4 = *(const float4*)(qp + it * 4);
            const int c = cb + it * 4;
            Qt[(c + 0) * 64 + row] = v4.x;
            Qt[(c + 1) * 64 + row] = v4.y;
            Qt[(c + 2) * 64 + row] = v4.z;
            Qt[(c + 3) * 64 + row] = v4.w;
        }
    }

    // Per-row factor: exp(gamma*ri) / scale(t),  scale(t)^2 = expm1(g*(t+1))/expm1(g)
    float rowfac[4];
#pragma unroll
    for (int i = 0; i < 4; i++) {
        const int t = t0 + r0 + i;
        const float sc2 = expm1f(gamma * (float)(t + 1)) / em1g;   // sum of decay row
        rowfac[i] = expf(gamma * (float)(r0 + i)) * rsqrtf(sc2);
    }

    float accV[4][8];
#pragma unroll
    for (int i = 0; i < 4; i++)
#pragma unroll
        for (int j = 0; j < 8; j++) accV[i][j] = 0.f;
    float rowAbs[4] = {0.f, 0.f, 0.f, 0.f};

    for (int s0 = 0; s0 <= t0; s0 += BKT) {
        // Load K tile transposed and V tile
        {
            const int row = tid >> 2;
            const int cb  = (tid & 3) * 16;
            const float* kp = qk + ((size_t)(b * T_ + s0 + row)) * (2 * C_) + C_ + (size_t)h * KD_ + cb;
#pragma unroll
            for (int it = 0; it < 4; it++) {
                float4 v4 = *(const float4*)(kp + it * 4);
                const int c = cb + it * 4;
                Kt[(c + 0) * 64 + row] = v4.x;
                Kt[(c + 1) * 64 + row] = v4.y;
                Kt[(c + 2) * 64 + row] = v4.z;
                Kt[(c + 3) * 64 + row] = v4.w;
            }
            const int vrow = tid >> 5;
            const int vc   = (tid & 31) * 4;
            const float* vp = vb + ((size_t)(b * T_ + s0)) * VBD_ + (size_t)h * VD_;
#pragma unroll
            for (int it = 0; it < 8; it++) {
                const int r = vrow + it * 8;
                *(float4*)&Vs[r * 128 + vc] =
                    *(const float4*)(vp + (size_t)r * VBD_ + vc);
            }
        }
        __syncthreads();

        // Per-column decay factor for this key tile
        float cf[4];
#pragma unroll
        for (int j = 0; j < 4; j++)
            cf[j] = expf(gamma * (float)(t0 - s0 - (c0 + j)));

        // S = Q.K^T (4x4 per thread)
        float s_[4][4];
#pragma unroll
        for (int i = 0; i < 4; i++)
#pragma unroll
            for (int j = 0; j < 4; j++) s_[i][j] = 0.f;

#pragma unroll 4
        for (int k = 0; k < 64; k += 4) {
            float4 qa[4], kb[4];
#pragma unroll
            for (int kk = 0; kk < 4; kk++) {
                qa[kk] = *(const float4*)&Qt[(k + kk) * 64 + r0];
                kb[kk] = *(const float4*)&Kt[(k + kk) * 64 + c0];
            }
#pragma unroll
            for (int kk = 0; kk < 4; kk++) {
                const float* qv = &qa[kk].x;
                const float* kv = &kb[kk].x;
#pragma unroll
                for (int i = 0; i < 4; i++)
#pragma unroll
                    for (int j = 0; j < 4; j++)
                        s_[i][j] = fmaf(qv[i], kv[j], s_[i][j]);
            }
        }

        // Apply decay mask + scale; causal mask on the diagonal tile.
        const bool diag = (s0 == t0);
#pragma unroll
        for (int i = 0; i < 4; i++) {
#pragma unroll
            for (int j = 0; j < 4; j++) {
                float v = s_[i][j] * rowfac[i] * cf[j];
                if (diag && (c0 + j) > (r0 + i)) v = 0.f;
                Ss[(r0 + i) * 65 + (c0 + j)] = v;
                rowAbs[i] += fabsf(v);
            }
        }
        __syncthreads();

        // accV += S @ V   (rows r0..r0+3, vcols tx*8..tx*8+7)
#pragma unroll 4
        for (int c = 0; c < 64; c++) {
            const float4 v0 = *(const float4*)&Vs[c * 128 + tx * 8];
            const float4 v1 = *(const float4*)&Vs[c * 128 + tx * 8 + 4];
#pragma unroll
            for (int i = 0; i < 4; i++) {
                const float sv = Ss[(r0 + i) * 65 + c];
                accV[i][0] = fmaf(sv, v0.x, accV[i][0]);
                accV[i][1] = fmaf(sv, v0.y, accV[i][1]);
                accV[i][2] = fmaf(sv, v0.z, accV[i][2]);
                accV[i][3] = fmaf(sv, v0.w, accV[i][3]);
                accV[i][4] = fmaf(sv, v1.x, accV[i][4]);
                accV[i][5] = fmaf(sv, v1.y, accV[i][5]);
                accV[i][6] = fmaf(sv, v1.z, accV[i][6]);
                accV[i][7] = fmaf(sv, v1.w, accV[i][7]);
            }
        }
        __syncthreads();
    }

    // Epilogue: denom -> RMSNorm -> gate -> store
    // Each row lives on 16 lanes (same half-warp); xor-reduce over tx (bits 0..3).
#pragma unroll
    for (int i = 0; i < 4; i++) {
        float ra = rowAbs[i];
        ra += __shfl_xor_sync(0xffffffffu, ra, 1);
        ra += __shfl_xor_sync(0xffffffffu, ra, 2);
        ra += __shfl_xor_sync(0xffffffffu, ra, 4);
        ra += __shfl_xor_sync(0xffffffffu, ra, 8);

        const float denom = fminf(fmaxf(ra, 1.0f), 50000.0f);
        const float inv   = 1.0f / denom;

        float r[8];
        float ss = 0.f;
#pragma unroll
        for (int j = 0; j < 8; j++) {
            r[j] = accV[i][j] * inv;
            ss  = fmaf(r[j], r[j], ss);
        }
        ss += __shfl_xor_sync(0xffffffffu, ss, 1);
        ss += __shfl_xor_sync(0xffffffffu, ss, 2);
        ss += __shfl_xor_sync(0xffffffffu, ss, 4);
        ss += __shfl_xor_sync(0xffffffffu, ss, 8);

        const float rstd = rsqrtf(ss * (1.0f / 128.0f) + 1.1920929e-7f);

        const int t = t0 + r0 + i;
        const size_t base = ((size_t)(b * T_ + t)) * VBD_ + (size_t)h * VD_ + tx * 8;
        const float4 g0 = *(const float4*)(gb + base);
        const float4 g1 = *(const float4*)(gb + base + 4);
        float4 o0, o1;
        o0.x = r[0] * rstd * g0.x;
        o0.y = r[1] * rstd * g0.y;
        o0.z = r[2] * rstd * g0.z;
        o0.w = r[3] * rstd * g0.w;
        o1.x = r[4] * rstd * g1.x;
        o1.y = r[5] * rstd * g1.y;
        o1.z = r[6] * rstd * g1.z;
        o1.w = r[7] * rstd * g1.w;
        *(float4*)(yb + base)     = o0;
        *(float4*)(yb + base + 4) = o1;
    }
}

// ---------------------------------------------------------------------------
// Small wrappers so SGEMMs can hit the device-global scratch without
// cudaGetSymbolAddress on the host side.
// ---------------------------------------------------------------------------
__global__ void __launch_bounds__(256)
sgemm_bias_to_qk(const float* __restrict__ A, const float* __restrict__ Bm,
                 const float* __restrict__ bias, int M, int N, int K);

extern "C" void kernel_launch(void* const* d_in, const int* in_sizes, int n_in,
                              void* d_out, int out_size)
{
    const float* x    = (const float*)d_in[0];
    const float* W_qk = (const float*)d_in[1];
    const float* b_qk = (const float*)d_in[2];
    const float* W_v  = (const float*)d_in[3];
    const float* b_v  = (const float*)d_in[4];
    const float* W_g  = (const float*)d_in[5];
    const float* b_g  = (const float*)d_in[6];
    const float* W_o  = (const float*)d_in[7];
    const float* b_o  = (const float*)d_in[8];
    float* out = (float*)d_out;

    // Resolve scratch addresses once per call (non-stream API; capture-safe,
    // but these are constant so failure modes are nil).
    static float* qkb  = nullptr;
    static float* vbuf = nullptr;
    static float* gbuf = nullptr;
    static float* ybuf = nullptr;
    if (!qkb) {
        cudaGetSymbolAddress((void**)&qkb,  g_qk);
        cudaGetSymbolAddress((void**)&vbuf, g_v);
        cudaGetSymbolAddress((void**)&gbuf, g_g);
        cudaGetSymbolAddress((void**)&ybuf, g_y);
        cudaFuncSetAttribute(retention_attn,
                             cudaFuncAttributeMaxDynamicSharedMemorySize,
                             ATT_SMEM_BYTES);
    }

    // Projections: x[4096,1024] @ W -> 2048 cols each
    dim3 gProj(2048 / 128, M_ / 128);
    sgemm_bias<128,128,8,8,8><<<gProj, 256>>>(x, W_qk, b_qk, qkb,  M_, 2048, C_);
    sgemm_bias<128,128,8,8,8><<<gProj, 256>>>(x, W_v,  b_v,  vbuf, M_, 2048, C_);
    sgemm_bias<128,128,8,8,8><<<gProj, 256>>>(x, W_g,  b_g,  gbuf, M_, 2048, C_);

    // Attention + RMSNorm + gating (reads/writes device globals directly)
    dim3 gAttn(T_ / BQ, H_, B_);
    retention_attn<<<gAttn, 256, ATT_SMEM_BYTES>>>();

    // Output projection: y[4096,2048] @ W_o[2048,1024]
    dim3 gOut(1024 / 128, M_ / 128);
    sgemm_bias<128,128,8,8,8><<<gOut, 256>>>(ybuf, W_o, b_o, out, M_, 1024, VBD_);

    (void)in_sizes; (void)n_in; (void)out_size;
}

// round 5
// speedup vs baseline: 1.7213x; 1.7213x over previous
#include <cuda_runtime.h>
#include <cuda_bf16.h>
#include <math.h>
#include <stdint.h>

// Problem constants
#define B_   2
#define T_   2048
#define C_   1024
#define H_   16
#define KD_  64
#define VD_  128
#define VBD_ 2048
#define M_   (B_ * T_)   // 4096 rows

// ---------------------------------------------------------------------------
// Scratch (static device globals -- no allocation allowed)
// ---------------------------------------------------------------------------
__device__ float g_qk[(size_t)M_ * 2048];   // [B*T, 2C]  q | k   (fp32)
__device__ float g_v [(size_t)M_ * 2048];   // [B*T, VBD]         (fp32)
__device__ float g_g [(size_t)M_ * 2048];   // [B*T, VBD] gate    (fp32)
__device__ float g_y [(size_t)M_ * 2048];   // [B*T, VBD] attn out (fp32)

// bf16x3 buffers.
// A-side ("rows"):  [R, 3K] = [hi | hi | lo]
// B-side ("trans"): [N, 3K] = [hi | lo | hi]
__device__ uint16_t g_x2  [(size_t)M_   * 3072];  // x     [4096, 3*1024]
__device__ uint16_t g_wqk2[(size_t)2048 * 3072];  // W_qk^T[2048, 3*1024]
__device__ uint16_t g_wv2 [(size_t)2048 * 3072];  // W_v^T [2048, 3*1024]
__device__ uint16_t g_wg2 [(size_t)2048 * 3072];  // W_g^T [2048, 3*1024]
__device__ uint16_t g_wo2 [(size_t)1024 * 6144];  // W_o^T [1024, 3*2048]
__device__ uint16_t g_y2  [(size_t)M_   * 6144];  // y     [4096, 3*2048]

// ---------------------------------------------------------------------------
// bf16 split helpers
// ---------------------------------------------------------------------------
__device__ __forceinline__ uint16_t f2bf(float x) {
    __nv_bfloat16 h = __float2bfloat16_rn(x);
    return *reinterpret_cast<uint16_t*>(&h);
}
__device__ __forceinline__ float bf2f(uint16_t u) {
    __nv_bfloat16 h = *reinterpret_cast<__nv_bfloat16*>(&u);
    return __bfloat162float(h);
}

// ---------------------------------------------------------------------------
// split_rows: fp32 [R,K] -> bf16 [R,3K] = [hi | hi | lo]   (A-side)
// ---------------------------------------------------------------------------
__global__ void __launch_bounds__(256)
split_rows(const float* __restrict__ in, uint16_t* __restrict__ out, int R, int K)
{
    const int q4 = K >> 2;
    int i = blockIdx.x * blockDim.x + threadIdx.x;
    if (i >= R * q4) return;
    const int m = i / q4, q = i % q4;
    float4 v = *(const float4*)(in + (size_t)m * K + q * 4);
    ushort4 hi, lo;
    hi.x = f2bf(v.x); lo.x = f2bf(v.x - bf2f(hi.x));
    hi.y = f2bf(v.y); lo.y = f2bf(v.y - bf2f(hi.y));
    hi.z = f2bf(v.z); lo.z = f2bf(v.z - bf2f(hi.z));
    hi.w = f2bf(v.w); lo.w = f2bf(v.w - bf2f(hi.w));
    uint16_t* o = out + (size_t)m * 3 * K + q * 4;
    *(ushort4*)(o)         = hi;   // seg0: hi
    *(ushort4*)(o + K)     = hi;   // seg1: hi
    *(ushort4*)(o + 2 * K) = lo;   // seg2: lo
}

// ---------------------------------------------------------------------------
// split_transpose: fp32 W[K,N] -> bf16 out[N,3K] = [hi | lo | hi]  (B-side)
// block (32,8), grid (N/32, K/32)
// ---------------------------------------------------------------------------
__global__ void __launch_bounds__(256)
split_transpose(const float* __restrict__ W, uint16_t* __restrict__ out, int K, int N)
{
    __shared__ float t[32][33];
    const int tx = threadIdx.x, ty = threadIdx.y;
    const int n0 = blockIdx.x * 32, k0 = blockIdx.y * 32;
#pragma unroll
    for (int j = 0; j < 4; j++)
        t[ty + j * 8][tx] = W[(size_t)(k0 + ty + j * 8) * N + n0 + tx];
    __syncthreads();
#pragma unroll
    for (int j = 0; j < 4; j++) {
        const int n = n0 + ty + j * 8;
        const float v = t[tx][ty + j * 8];
        const uint16_t hi = f2bf(v);
        const uint16_t lo = f2bf(v - bf2f(hi));
        uint16_t* o = out + (size_t)n * 3 * K + k0 + tx;
        o[0]     = hi;   // seg0: hi
        o[K]     = lo;   // seg1: lo
        o[2 * K] = hi;   // seg2: hi
    }
}

// ---------------------------------------------------------------------------
// Baseline-ISA tensor core helpers (sm_80-level: ldmatrix / mma.sync / cp.async)
// ---------------------------------------------------------------------------
__device__ __forceinline__ uint32_t smem_u32(const void* p) {
    uint32_t a;
    asm("{ .reg .u64 t; cvta.to.shared.u64 t, %1; cvt.u32.u64 %0, t; }" : "=r"(a) : "l"(p));
    return a;
}
__device__ __forceinline__ void cp_async16(uint32_t dst, const void* src) {
    asm volatile("cp.async.cg.shared.global [%0], [%1], 16;" :: "r"(dst), "l"(src));
}
__device__ __forceinline__ void cp_commit() {
    asm volatile("cp.async.commit_group;" ::: "memory");
}
template <int N>
__device__ __forceinline__ void cp_wait() {
    asm volatile("cp.async.wait_group %0;" :: "n"(N) : "memory");
}
__device__ __forceinline__ void ldmatrix_x4(uint32_t* r, uint32_t addr) {
    asm volatile("ldmatrix.sync.aligned.m8n8.x4.shared.b16 {%0,%1,%2,%3}, [%4];"
                 : "=r"(r[0]), "=r"(r[1]), "=r"(r[2]), "=r"(r[3]) : "r"(addr));
}
__device__ __forceinline__ void mma16816(float* d, const uint32_t* a, uint32_t b0, uint32_t b1) {
    asm volatile(
        "mma.sync.aligned.m16n8k16.row.col.f32.bf16.bf16.f32 "
        "{%0,%1,%2,%3}, {%4,%5,%6,%7}, {%8,%9}, {%0,%1,%2,%3};"
        : "+f"(d[0]), "+f"(d[1]), "+f"(d[2]), "+f"(d[3])
        : "r"(a[0]), "r"(a[1]), "r"(a[2]), "r"(a[3]), "r"(b0), "r"(b1));
}

// ---------------------------------------------------------------------------
// mma.sync bf16x3 GEMM: C[M,N] = A2[M,K2] . B2[N,K2]^T + bias
// CTA 128x128, 8 warps (2x4), warp tile 64x32, BK=64 bf16 (128B rows, XOR swizzle).
// 2-stage cp.async pipeline. grid = (N/128, M/128), 256 threads.
// ---------------------------------------------------------------------------
#define GEMM_SMEM_BYTES (2 * 2 * 16384)   // 2 stages x (A 16K + B 16K) = 64 KB

__global__ void __launch_bounds__(256)
gemm_bf16split(const uint16_t* __restrict__ A2, const uint16_t* __restrict__ B2,
               const float* __restrict__ bias, float* __restrict__ Cm,
               int K2, int N)
{
    extern __shared__ __align__(128) char smx[];
    const uint32_t sb = smem_u32(smx);

    const int tid = threadIdx.x;
    const int wid = tid >> 5;
    const int lid = tid & 31;
    const int m0 = blockIdx.y * 128;
    const int n0 = blockIdx.x * 128;
    const int wm = (wid & 1) * 64;   // warp m offset in tile
    const int wn = (wid >> 1) * 32;  // warp n offset in tile

    float acc[4][4][4];              // [mt][nt][reg]
#pragma unroll
    for (int i = 0; i < 4; i++)
#pragma unroll
        for (int j = 0; j < 4; j++)
#pragma unroll
            for (int r = 0; r < 4; r++) acc[i][j][r] = 0.f;

    // load-issue helper: chunk c into stage s (A & B, 128x64 bf16 each, swizzled)
    auto issue = [&](int c, int s) {
        const int kk = c * 64;
        const uint32_t stA = sb + s * 32768;
        const uint32_t stB = stA + 16384;
#pragma unroll
        for (int it = 0; it < 4; it++) {
            const int unit = tid + it * 256;     // 0..1023
            const int row  = unit >> 3;
            const int u    = unit & 7;
            const uint32_t off = row * 128 + ((u ^ (row & 7)) * 16);
            cp_async16(stA + off, A2 + (size_t)(m0 + row) * K2 + kk + u * 8);
            cp_async16(stB + off, B2 + (size_t)(n0 + row) * K2 + kk + u * 8);
        }
        cp_commit();
    };

    const int NC = K2 >> 6;
    issue(0, 0);

    for (int c = 0; c < NC; ++c) {
        if (c + 1 < NC) { issue(c + 1, (c + 1) & 1); cp_wait<1>(); }
        else            { cp_wait<0>(); }
        __syncthreads();

        const int s = c & 1;
        const uint32_t aB = sb + s * 32768;
        const uint32_t bB = aB + 16384;

#pragma unroll
        for (int ks = 0; ks < 4; ks++) {
            const int q = lid >> 3;              // quad 0..3
            const int l7 = lid & 7;

            uint32_t af[4][4];
#pragma unroll
            for (int mt = 0; mt < 4; mt++) {
                const int row = wm + mt * 16 + (q & 1) * 8 + l7;
                const int su  = (ks * 2 + (q >> 1)) ^ (row & 7);
                ldmatrix_x4(af[mt], aB + row * 128 + su * 16);
            }
            uint32_t bf[2][4];
#pragma unroll
            for (int np = 0; np < 2; np++) {
                const int row = wn + np * 16 + (q >> 1) * 8 + l7;
                const int su  = (ks * 2 + (q & 1)) ^ (row & 7);
                ldmatrix_x4(bf[np], bB + row * 128 + su * 16);
            }
#pragma unroll
            for (int mt = 0; mt < 4; mt++)
#pragma unroll
                for (int nt = 0; nt < 4; nt++)
                    mma16816(acc[mt][nt], af[mt],
                             bf[nt >> 1][(nt & 1) * 2], bf[nt >> 1][(nt & 1) * 2 + 1]);
        }
        __syncthreads();
    }

    // Epilogue: d-reg mapping for m16n8: row = (lid>>2) [+8], col = (lid&3)*2 [+1]
    const int gr = lid >> 2;
    const int gc = (lid & 3) * 2;
#pragma unroll
    for (int mt = 0; mt < 4; mt++) {
        const int row = m0 + wm + mt * 16 + gr;
#pragma unroll
        for (int nt = 0; nt < 4; nt++) {
            const int col = n0 + wn + nt * 8 + gc;
            const float b0 = __ldg(&bias[col]);
            const float b1 = __ldg(&bias[col + 1]);
            float2 o0, o1;
            o0.x = acc[mt][nt][0] + b0;
            o0.y = acc[mt][nt][1] + b1;
            o1.x = acc[mt][nt][2] + b0;
            o1.y = acc[mt][nt][3] + b1;
            *(float2*)(Cm + (size_t)row * N + col)       = o0;
            *(float2*)(Cm + (size_t)(row + 8) * N + col) = o1;
        }
    }
}

// ---------------------------------------------------------------------------
// Retention attention core, fused with RMSNorm + gating (unchanged from R2 pass).
// ---------------------------------------------------------------------------
#define BQ  64
#define BKT 64
#define ATT_SMEM_FLOATS (64*64 + 64*64 + 64*65 + 64*128)
#define ATT_SMEM_BYTES  (ATT_SMEM_FLOATS * 4)

__global__ void __launch_bounds__(256)
retention_attn()
{
    extern __shared__ float sm[];
    float* Qt = sm;                    // [k][r]  64x64 transposed
    float* Kt = Qt + 64 * 64;          // [k][s]  64x64 transposed
    float* Ss = Kt + 64 * 64;          // [r][c]  64x65 (padded)
    float* Vs = Ss + 64 * 65;          // [s][v]  64x128

    const float* qk = g_qk;
    const float* vb = g_v;
    const float* gb = g_g;
    float*       yb = g_y;

    const int tid = threadIdx.x;
    const int ty  = tid >> 4;
    const int tx  = tid & 15;
    const int r0  = ty * 4;
    const int c0  = tx * 4;

    const int qi = blockIdx.x;
    const int h  = blockIdx.y;
    const int b  = blockIdx.z;
    const int t0 = qi * BQ;

    const float gamma = log1pf(-exp2f(-5.0f - (float)h));
    const float em1g  = expm1f(gamma);

    {
        const int row = tid >> 2;
        const int cb  = (tid & 3) * 16;
        const float* qp = qk + ((size_t)(b * T_ + t0 + row)) * (2 * C_) + (size_t)h * KD_ + cb;
#pragma unroll
        for (int it = 0; it < 4; it++) {
            float4 v4 = *(const float4*)(qp + it * 4);
            const int c = cb + it * 4;
            Qt[(c + 0) * 64 + row] = v4.x;
            Qt[(c + 1) * 64 + row] = v4.y;
            Qt[(c + 2) * 64 + row] = v4.z;
            Qt[(c + 3) * 64 + row] = v4.w;
        }
    }

    float rowfac[4];
#pragma unroll
    for (int i = 0; i < 4; i++) {
        const int t = t0 + r0 + i;
        const float sc2 = expm1f(gamma * (float)(t + 1)) / em1g;
        rowfac[i] = expf(gamma * (float)(r0 + i)) * rsqrtf(sc2);
    }

    float accV[4][8];
#pragma unroll
    for (int i = 0; i < 4; i++)
#pragma unroll
        for (int j = 0; j < 8; j++) accV[i][j] = 0.f;
    float rowAbs[4] = {0.f, 0.f, 0.f, 0.f};

    for (int s0 = 0; s0 <= t0; s0 += BKT) {
        {
            const int row = tid >> 2;
            const int cb  = (tid & 3) * 16;
            const float* kp = qk + ((size_t)(b * T_ + s0 + row)) * (2 * C_) + C_ + (size_t)h * KD_ + cb;
#pragma unroll
            for (int it = 0; it < 4; it++) {
                float4 v4 = *(const float4*)(kp + it * 4);
                const int c = cb + it * 4;
                Kt[(c + 0) * 64 + row] = v4.x;
                Kt[(c + 1) * 64 + row] = v4.y;
                Kt[(c + 2) * 64 + row] = v4.z;
                Kt[(c + 3) * 64 + row] = v4.w;
            }
            const int vrow = tid >> 5;
            const int vc   = (tid & 31) * 4;
            const float* vp = vb + ((size_t)(b * T_ + s0)) * VBD_ + (size_t)h * VD_;
#pragma unroll
            for (int it = 0; it < 8; it++) {
                const int r = vrow + it * 8;
                *(float4*)&Vs[r * 128 + vc] =
                    *(const float4*)(vp + (size_t)r * VBD_ + vc);
            }
        }
        __syncthreads();

        float cf[4];
#pragma unroll
        for (int j = 0; j < 4; j++)
            cf[j] = expf(gamma * (float)(t0 - s0 - (c0 + j)));

        float s_[4][4];
#pragma unroll
        for (int i = 0; i < 4; i++)
#pragma unroll
            for (int j = 0; j < 4; j++) s_[i][j] = 0.f;

#pragma unroll 4
        for (int k = 0; k < 64; k += 4) {
            float4 qa[4], kb[4];
#pragma unroll
            for (int kk = 0; kk < 4; kk++) {
                qa[kk] = *(const float4*)&Qt[(k + kk) * 64 + r0];
                kb[kk] = *(const float4*)&Kt[(k + kk) * 64 + c0];
            }
#pragma unroll
            for (int kk = 0; kk < 4; kk++) {
                const float* qv = &qa[kk].x;
                const float* kv = &kb[kk].x;
#pragma unroll
                for (int i = 0; i < 4; i++)
#pragma unroll
                    for (int j = 0; j < 4; j++)
                        s_[i][j] = fmaf(qv[i], kv[j], s_[i][j]);
            }
        }

        const bool diag = (s0 == t0);
#pragma unroll
        for (int i = 0; i < 4; i++) {
#pragma unroll
            for (int j = 0; j < 4; j++) {
                float v = s_[i][j] * rowfac[i] * cf[j];
                if (diag && (c0 + j) > (r0 + i)) v = 0.f;
                Ss[(r0 + i) * 65 + (c0 + j)] = v;
                rowAbs[i] += fabsf(v);
            }
        }
        __syncthreads();

#pragma unroll 4
        for (int c = 0; c < 64; c++) {
            const float4 v0 = *(const float4*)&Vs[c * 128 + tx * 8];
            const float4 v1 = *(const float4*)&Vs[c * 128 + tx * 8 + 4];
#pragma unroll
            for (int i = 0; i < 4; i++) {
                const float sv = Ss[(r0 + i) * 65 + c];
                accV[i][0] = fmaf(sv, v0.x, accV[i][0]);
                accV[i][1] = fmaf(sv, v0.y, accV[i][1]);
                accV[i][2] = fmaf(sv, v0.z, accV[i][2]);
                accV[i][3] = fmaf(sv, v0.w, accV[i][3]);
                accV[i][4] = fmaf(sv, v1.x, accV[i][4]);
                accV[i][5] = fmaf(sv, v1.y, accV[i][5]);
                accV[i][6] = fmaf(sv, v1.z, accV[i][6]);
                accV[i][7] = fmaf(sv, v1.w, accV[i][7]);
            }
        }
        __syncthreads();
    }

#pragma unroll
    for (int i = 0; i < 4; i++) {
        float ra = rowAbs[i];
        ra += __shfl_xor_sync(0xffffffffu, ra, 1);
        ra += __shfl_xor_sync(0xffffffffu, ra, 2);
        ra += __shfl_xor_sync(0xffffffffu, ra, 4);
        ra += __shfl_xor_sync(0xffffffffu, ra, 8);

        const float denom = fminf(fmaxf(ra, 1.0f), 50000.0f);
        const float inv   = 1.0f / denom;

        float r[8];
        float ss = 0.f;
#pragma unroll
        for (int j = 0; j < 8; j++) {
            r[j] = accV[i][j] * inv;
            ss  = fmaf(r[j], r[j], ss);
        }
        ss += __shfl_xor_sync(0xffffffffu, ss, 1);
        ss += __shfl_xor_sync(0xffffffffu, ss, 2);
        ss += __shfl_xor_sync(0xffffffffu, ss, 4);
        ss += __shfl_xor_sync(0xffffffffu, ss, 8);

        const float rstd = rsqrtf(ss * (1.0f / 128.0f) + 1.1920929e-7f);

        const int t = t0 + r0 + i;
        const size_t base = ((size_t)(b * T_ + t)) * VBD_ + (size_t)h * VD_ + tx * 8;
        const float4 g0 = *(const float4*)(gb + base);
        const float4 g1 = *(const float4*)(gb + base + 4);
        float4 o0, o1;
        o0.x = r[0] * rstd * g0.x;
        o0.y = r[1] * rstd * g0.y;
        o0.z = r[2] * rstd * g0.z;
        o0.w = r[3] * rstd * g0.w;
        o1.x = r[4] * rstd * g1.x;
        o1.y = r[5] * rstd * g1.y;
        o1.z = r[6] * rstd * g1.z;
        o1.w = r[7] * rstd * g1.w;
        *(float4*)(yb + base)     = o0;
        *(float4*)(yb + base + 4) = o1;
    }
}

// ---------------------------------------------------------------------------
// Launch
// ---------------------------------------------------------------------------
extern "C" void kernel_launch(void* const* d_in, const int* in_sizes, int n_in,
                              void* d_out, int out_size)
{
    const float* x    = (const float*)d_in[0];
    const float* W_qk = (const float*)d_in[1];
    const float* b_qk = (const float*)d_in[2];
    const float* W_v  = (const float*)d_in[3];
    const float* b_v  = (const float*)d_in[4];
    const float* W_g  = (const float*)d_in[5];
    const float* b_g  = (const float*)d_in[6];
    const float* W_o  = (const float*)d_in[7];
    const float* b_o  = (const float*)d_in[8];
    float* out = (float*)d_out;

    float *qkb, *vbuf, *gbuf, *ybuf;
    uint16_t *x2, *wqk2, *wv2, *wg2, *wo2, *y2;
    cudaGetSymbolAddress((void**)&qkb,  g_qk);
    cudaGetSymbolAddress((void**)&vbuf, g_v);
    cudaGetSymbolAddress((void**)&gbuf, g_g);
    cudaGetSymbolAddress((void**)&ybuf, g_y);
    cudaGetSymbolAddress((void**)&x2,   g_x2);
    cudaGetSymbolAddress((void**)&wqk2, g_wqk2);
    cudaGetSymbolAddress((void**)&wv2,  g_wv2);
    cudaGetSymbolAddress((void**)&wg2,  g_wg2);
    cudaGetSymbolAddress((void**)&wo2,  g_wo2);
    cudaGetSymbolAddress((void**)&y2,   g_y2);
    cudaFuncSetAttribute(retention_attn,
                         cudaFuncAttributeMaxDynamicSharedMemorySize, ATT_SMEM_BYTES);
    cudaFuncSetAttribute(gemm_bf16split,
                         cudaFuncAttributeMaxDynamicSharedMemorySize, GEMM_SMEM_BYTES);

    // --- split/transpose operands to bf16x3 layouts ---
    {
        split_rows<<<(M_ * (C_ / 4) + 255) / 256, 256>>>(x, x2, M_, C_);
        dim3 bt(32, 8);
        split_transpose<<<dim3(2048 / 32, 1024 / 32), bt>>>(W_qk, wqk2, 1024, 2048);
        split_transpose<<<dim3(2048 / 32, 1024 / 32), bt>>>(W_v,  wv2,  1024, 2048);
        split_transpose<<<dim3(2048 / 32, 1024 / 32), bt>>>(W_g,  wg2,  1024, 2048);
        split_transpose<<<dim3(1024 / 32, 2048 / 32), bt>>>(W_o,  wo2,  2048, 1024);
    }

    // --- projection GEMMs (mma.sync bf16x3): K2 = 3*1024 = 3072 ---
    {
        dim3 g(2048 / 128, M_ / 128);
        gemm_bf16split<<<g, 256, GEMM_SMEM_BYTES>>>(x2, wqk2, b_qk, qkb,  3072, 2048);
        gemm_bf16split<<<g, 256, GEMM_SMEM_BYTES>>>(x2, wv2,  b_v,  vbuf, 3072, 2048);
        gemm_bf16split<<<g, 256, GEMM_SMEM_BYTES>>>(x2, wg2,  b_g,  gbuf, 3072, 2048);
    }

    // --- attention + RMSNorm + gating ---
    {
        dim3 gAttn(T_ / BQ, H_, B_);
        retention_attn<<<gAttn, 256, ATT_SMEM_BYTES>>>();
    }

    // --- split y, output GEMM: K2 = 3*2048 = 6144 ---
    {
        split_rows<<<(M_ * (VBD_ / 4) + 255) / 256, 256>>>(ybuf, y2, M_, VBD_);
        dim3 g(1024 / 128, M_ / 128);
        gemm_bf16split<<<g, 256, GEMM_SMEM_BYTES>>>(y2, wo2, b_o, out, 6144, 1024);
    }

    (void)in_sizes; (void)n_in; (void)out_size;
}

// round 6
// speedup vs baseline: 2.8047x; 1.6294x over previous
#include <cuda_runtime.h>
#include <cuda_bf16.h>
#include <math.h>
#include <stdint.h>

// Problem constants
#define B_   2
#define T_   2048
#define C_   1024
#define H_   16
#define KD_  64
#define VD_  128
#define VBD_ 2048
#define M_   (B_ * T_)   // 4096 rows

// ---------------------------------------------------------------------------
// Scratch (static device globals -- no allocation allowed)
// ---------------------------------------------------------------------------
__device__ float g_qk[(size_t)M_ * 2048];   // [B*T, 2C]  q | k   (fp32)
__device__ float g_v [(size_t)M_ * 2048];   // [B*T, VBD]         (fp32)
__device__ float g_g [(size_t)M_ * 2048];   // [B*T, VBD] gate    (fp32)
__device__ float g_y [(size_t)M_ * 2048];   // [B*T, VBD] attn out (fp32)

// bf16x3 buffers for projection GEMMs.
__device__ uint16_t g_x2  [(size_t)M_   * 3072];  // x     [4096, 3*1024]  hi|hi|lo
__device__ uint16_t g_wqk2[(size_t)2048 * 3072];  // W_qk^T[2048, 3*1024]  hi|lo|hi
__device__ uint16_t g_wv2 [(size_t)2048 * 3072];  // W_v^T
__device__ uint16_t g_wg2 [(size_t)2048 * 3072];  // W_g^T
__device__ uint16_t g_wo2 [(size_t)1024 * 6144];  // W_o^T [1024, 3*2048]  hi|lo|hi
__device__ uint16_t g_y2  [(size_t)M_   * 6144];  // y     [4096, 3*2048]  hi|hi|lo

// bf16x3 attention operands (head-major)
__device__ uint16_t g_q2 [(size_t)B_ * H_ * T_ * 192];   // [bh, t, 192] hi|hi|lo
__device__ uint16_t g_k2 [(size_t)B_ * H_ * T_ * 192];   // [bh, t, 192] hi|lo|hi
__device__ uint16_t g_vt2[(size_t)B_ * H_ * VD_ * 6144]; // [bh, v, 3*2048] hi|lo|hi over s

// ---------------------------------------------------------------------------
// bf16 split helpers
// ---------------------------------------------------------------------------
__device__ __forceinline__ uint16_t f2bf(float x) {
    __nv_bfloat16 h = __float2bfloat16_rn(x);
    return *reinterpret_cast<uint16_t*>(&h);
}
__device__ __forceinline__ float bf2f(uint16_t u) {
    __nv_bfloat16 h = *reinterpret_cast<__nv_bfloat16*>(&u);
    return __bfloat162float(h);
}

// ---------------------------------------------------------------------------
// split_rows: fp32 [R,K] -> bf16 [R,3K] = [hi | hi | lo]   (A-side)
// ---------------------------------------------------------------------------
__global__ void __launch_bounds__(256)
split_rows(const float* __restrict__ in, uint16_t* __restrict__ out, int R, int K)
{
    const int q4 = K >> 2;
    int i = blockIdx.x * blockDim.x + threadIdx.x;
    if (i >= R * q4) return;
    const int m = i / q4, q = i % q4;
    float4 v = *(const float4*)(in + (size_t)m * K + q * 4);
    ushort4 hi, lo;
    hi.x = f2bf(v.x); lo.x = f2bf(v.x - bf2f(hi.x));
    hi.y = f2bf(v.y); lo.y = f2bf(v.y - bf2f(hi.y));
    hi.z = f2bf(v.z); lo.z = f2bf(v.z - bf2f(hi.z));
    hi.w = f2bf(v.w); lo.w = f2bf(v.w - bf2f(hi.w));
    uint16_t* o = out + (size_t)m * 3 * K + q * 4;
    *(ushort4*)(o)         = hi;
    *(ushort4*)(o + K)     = hi;
    *(ushort4*)(o + 2 * K) = lo;
}

// ---------------------------------------------------------------------------
// split_transpose: fp32 W[K,N] -> bf16 out[N,3K] = [hi | lo | hi]  (B-side)
// ---------------------------------------------------------------------------
__global__ void __launch_bounds__(256)
split_transpose(const float* __restrict__ W, uint16_t* __restrict__ out, int K, int N)
{
    __shared__ float t[32][33];
    const int tx = threadIdx.x, ty = threadIdx.y;
    const int n0 = blockIdx.x * 32, k0 = blockIdx.y * 32;
#pragma unroll
    for (int j = 0; j < 4; j++)
        t[ty + j * 8][tx] = W[(size_t)(k0 + ty + j * 8) * N + n0 + tx];
    __syncthreads();
#pragma unroll
    for (int j = 0; j < 4; j++) {
        const int n = n0 + ty + j * 8;
        const float v = t[tx][ty + j * 8];
        const uint16_t hi = f2bf(v);
        const uint16_t lo = f2bf(v - bf2f(hi));
        uint16_t* o = out + (size_t)n * 3 * K + k0 + tx;
        o[0]     = hi;
        o[K]     = lo;
        o[2 * K] = hi;
    }
}

// ---------------------------------------------------------------------------
// split_qk_heads: g_qk [B*T, 2048] -> g_q2/g_k2 [bh, t, 192]
// q: hi|hi|lo ; k: hi|lo|hi.  1 thread = 1 float4 of one head.
// ---------------------------------------------------------------------------
__global__ void __launch_bounds__(256)
split_qk_heads()
{
    int i = blockIdx.x * blockDim.x + threadIdx.x;    // 0 .. M_*H_*16-1
    if (i >= M_ * H_ * 16) return;
    const int d4 = i & 15;
    const int h  = (i >> 4) & 15;
    const int bt = i >> 8;
    const int b  = bt >> 11;          // t = bt & 2047
    const int t  = bt & 2047;
    const size_t base = (size_t)bt * 2048 + h * 64 + d4 * 4;
    float4 qv = *(const float4*)(g_qk + base);
    float4 kv = *(const float4*)(g_qk + base + 1024);

    ushort4 qh, ql, kh, kl;
    qh.x = f2bf(qv.x); ql.x = f2bf(qv.x - bf2f(qh.x));
    qh.y = f2bf(qv.y); ql.y = f2bf(qv.y - bf2f(qh.y));
    qh.z = f2bf(qv.z); ql.z = f2bf(qv.z - bf2f(qh.z));
    qh.w = f2bf(qv.w); ql.w = f2bf(qv.w - bf2f(qh.w));
    kh.x = f2bf(kv.x); kl.x = f2bf(kv.x - bf2f(kh.x));
    kh.y = f2bf(kv.y); kl.y = f2bf(kv.y - bf2f(kh.y));
    kh.z = f2bf(kv.z); kl.z = f2bf(kv.z - bf2f(kh.z));
    kh.w = f2bf(kv.w); kl.w = f2bf(kv.w - bf2f(kh.w));

    const size_t ob = ((size_t)(b * H_ + h) * T_ + t) * 192 + d4 * 4;
    *(ushort4*)(g_q2 + ob)       = qh;
    *(ushort4*)(g_q2 + ob + 64)  = qh;
    *(ushort4*)(g_q2 + ob + 128) = ql;
    *(ushort4*)(g_k2 + ob)       = kh;
    *(ushort4*)(g_k2 + ob + 64)  = kl;
    *(ushort4*)(g_k2 + ob + 128) = kh;
}

// ---------------------------------------------------------------------------
// transpose_split_v: g_v [B*T, 2048] -> g_vt2 [bh, v, 3*2048] (hi|lo|hi over s)
// grid (T/32, VD/32, B*H), block (32,8)
// ---------------------------------------------------------------------------
__global__ void __launch_bounds__(256)
transpose_split_v()
{
    __shared__ float t[32][33];
    const int tx = threadIdx.x, ty = threadIdx.y;
    const int s0 = blockIdx.x * 32;
    const int v0 = blockIdx.y * 32;
    const int bh = blockIdx.z;
    const int b  = bh >> 4;
    const int h  = bh & 15;
#pragma unroll
    for (int j = 0; j < 4; j++)
        t[ty + j * 8][tx] = g_v[(size_t)(b * T_ + s0 + ty + j * 8) * 2048 + h * 128 + v0 + tx];
    __syncthreads();
#pragma unroll
    for (int j = 0; j < 4; j++) {
        const int v = v0 + ty + j * 8;
        const float x = t[tx][ty + j * 8];
        const uint16_t hi = f2bf(x);
        const uint16_t lo = f2bf(x - bf2f(hi));
        uint16_t* o = g_vt2 + ((size_t)bh * 128 + v) * 6144 + s0 + tx;
        o[0]    = hi;
        o[2048] = lo;
        o[4096] = hi;
    }
}

// ---------------------------------------------------------------------------
// Baseline-ISA tensor core helpers
// ---------------------------------------------------------------------------
__device__ __forceinline__ uint32_t smem_u32(const void* p) {
    uint32_t a;
    asm("{ .reg .u64 t; cvta.to.shared.u64 t, %1; cvt.u32.u64 %0, t; }" : "=r"(a) : "l"(p));
    return a;
}
__device__ __forceinline__ void cp_async16(uint32_t dst, const void* src) {
    asm volatile("cp.async.cg.shared.global [%0], [%1], 16;" :: "r"(dst), "l"(src));
}
__device__ __forceinline__ void cp_commit() {
    asm volatile("cp.async.commit_group;" ::: "memory");
}
template <int N>
__device__ __forceinline__ void cp_wait() {
    asm volatile("cp.async.wait_group %0;" :: "n"(N) : "memory");
}
__device__ __forceinline__ void ldmatrix_x4(uint32_t* r, uint32_t addr) {
    asm volatile("ldmatrix.sync.aligned.m8n8.x4.shared.b16 {%0,%1,%2,%3}, [%4];"
                 : "=r"(r[0]), "=r"(r[1]), "=r"(r[2]), "=r"(r[3]) : "r"(addr));
}
__device__ __forceinline__ void mma16816(float* d, const uint32_t* a, uint32_t b0, uint32_t b1) {
    asm volatile(
        "mma.sync.aligned.m16n8k16.row.col.f32.bf16.bf16.f32 "
        "{%0,%1,%2,%3}, {%4,%5,%6,%7}, {%8,%9}, {%0,%1,%2,%3};"
        : "+f"(d[0]), "+f"(d[1]), "+f"(d[2]), "+f"(d[3])
        : "r"(a[0]), "r"(a[1]), "r"(a[2]), "r"(a[3]), "r"(b0), "r"(b1));
}

// ---------------------------------------------------------------------------
// mma.sync bf16x3 GEMM (unchanged from R5 pass)
// ---------------------------------------------------------------------------
#define GEMM_SMEM_BYTES (2 * 2 * 16384)

__global__ void __launch_bounds__(256)
gemm_bf16split(const uint16_t* __restrict__ A2, const uint16_t* __restrict__ B2,
               const float* __restrict__ bias, float* __restrict__ Cm,
               int K2, int N)
{
    extern __shared__ __align__(128) char smx[];
    const uint32_t sb = smem_u32(smx);

    const int tid = threadIdx.x;
    const int wid = tid >> 5;
    const int lid = tid & 31;
    const int m0 = blockIdx.y * 128;
    const int n0 = blockIdx.x * 128;
    const int wm = (wid & 1) * 64;
    const int wn = (wid >> 1) * 32;

    float acc[4][4][4];
#pragma unroll
    for (int i = 0; i < 4; i++)
#pragma unroll
        for (int j = 0; j < 4; j++)
#pragma unroll
            for (int r = 0; r < 4; r++) acc[i][j][r] = 0.f;

    auto issue = [&](int c, int s) {
        const int kk = c * 64;
        const uint32_t stA = sb + s * 32768;
        const uint32_t stB = stA + 16384;
#pragma unroll
        for (int it = 0; it < 4; it++) {
            const int unit = tid + it * 256;
            const int row  = unit >> 3;
            const int u    = unit & 7;
            const uint32_t off = row * 128 + ((u ^ (row & 7)) * 16);
            cp_async16(stA + off, A2 + (size_t)(m0 + row) * K2 + kk + u * 8);
            cp_async16(stB + off, B2 + (size_t)(n0 + row) * K2 + kk + u * 8);
        }
        cp_commit();
    };

    const int NC = K2 >> 6;
    issue(0, 0);

    for (int c = 0; c < NC; ++c) {
        if (c + 1 < NC) { issue(c + 1, (c + 1) & 1); cp_wait<1>(); }
        else            { cp_wait<0>(); }
        __syncthreads();

        const int s = c & 1;
        const uint32_t aB = sb + s * 32768;
        const uint32_t bB = aB + 16384;

#pragma unroll
        for (int ks = 0; ks < 4; ks++) {
            const int q = lid >> 3;
            const int l7 = lid & 7;

            uint32_t af[4][4];
#pragma unroll
            for (int mt = 0; mt < 4; mt++) {
                const int row = wm + mt * 16 + (q & 1) * 8 + l7;
                const int su  = (ks * 2 + (q >> 1)) ^ (row & 7);
                ldmatrix_x4(af[mt], aB + row * 128 + su * 16);
            }
            uint32_t bf[2][4];
#pragma unroll
            for (int np = 0; np < 2; np++) {
                const int row = wn + np * 16 + (q >> 1) * 8 + l7;
                const int su  = (ks * 2 + (q & 1)) ^ (row & 7);
                ldmatrix_x4(bf[np], bB + row * 128 + su * 16);
            }
#pragma unroll
            for (int mt = 0; mt < 4; mt++)
#pragma unroll
                for (int nt = 0; nt < 4; nt++)
                    mma16816(acc[mt][nt], af[mt],
                             bf[nt >> 1][(nt & 1) * 2], bf[nt >> 1][(nt & 1) * 2 + 1]);
        }
        __syncthreads();
    }

    const int gr = lid >> 2;
    const int gc = (lid & 3) * 2;
#pragma unroll
    for (int mt = 0; mt < 4; mt++) {
        const int row = m0 + wm + mt * 16 + gr;
#pragma unroll
        for (int nt = 0; nt < 4; nt++) {
            const int col = n0 + wn + nt * 8 + gc;
            const float b0 = __ldg(&bias[col]);
            const float b1 = __ldg(&bias[col + 1]);
            float2 o0, o1;
            o0.x = acc[mt][nt][0] + b0;
            o0.y = acc[mt][nt][1] + b1;
            o1.x = acc[mt][nt][2] + b0;
            o1.y = acc[mt][nt][3] + b1;
            *(float2*)(Cm + (size_t)row * N + col)       = o0;
            *(float2*)(Cm + (size_t)(row + 8) * N + col) = o1;
        }
    }
}

// ---------------------------------------------------------------------------
// mma.sync retention attention (bf16x3), fused RMSNorm + gating.
// CTA = 64 query rows x one (b,h).  8 warps: m_w = wid&3 (16 rows each),
// n_w = wid>>2 (score cols n_w*32.. / out cols n_w*64..).
// smem layout (bytes):
//   Q2s   @ 0       : 3 chunks x (64 x 128B)   = 24576
//   S2s   @ 24576   : 3 chunks x (64 x 128B)   = 24576
//   K2s   @ 49152   : 2 stages x 24576         = 49152
//   Vts   @ 98304   : 2 stages x 3 x (128x128B)= 98304
//   rowAbs@ 196608  : 64 floats
//   rss   @ 196864  : 128 floats
// ---------------------------------------------------------------------------
#define AT_SQ   0
#define AT_SS   24576
#define AT_SK   49152
#define AT_SV   98304
#define AT_RA   196608
#define AT_RS   196864
#define AT_SMEM 197376

__global__ void __launch_bounds__(256)
retention_attn_mma()
{
    extern __shared__ __align__(128) char smx[];
    const uint32_t sb = smem_u32(smx);
    float* rowAbsS = (float*)(smx + AT_RA);
    float* rssS    = (float*)(smx + AT_RS);

    const int tid = threadIdx.x;
    const int wid = tid >> 5;
    const int lid = tid & 31;
    const int q   = lid >> 3;
    const int l7  = lid & 7;
    const int m_w = wid & 3;
    const int n_w = wid >> 2;
    const int gr  = lid >> 2;
    const int gc  = (lid & 3) * 2;

    const int qi = gridDim.x - 1 - blockIdx.x;   // big CTAs first
    const int h  = blockIdx.y;
    const int b  = blockIdx.z;
    const int t0 = qi * 64;
    const int bh = b * H_ + h;

    const float gamma = log1pf(-exp2f(-5.0f - (float)h));
    const float em1g  = expm1f(gamma);

    // per-thread row constants (rows r0 = m_w*16+gr, r1 = r0+8)
    const int r0 = m_w * 16 + gr;
    const int r1 = r0 + 8;
    float rowfac[2];
#pragma unroll
    for (int hrow = 0; hrow < 2; hrow++) {
        const int rl = r0 + hrow * 8;
        const int t  = t0 + rl;
        const float sc2 = expm1f(gamma * (float)(t + 1)) / em1g;
        rowfac[hrow] = expf(gamma * (float)rl) * rsqrtf(sc2);
    }
    // per-thread col decay: ecl[nt][cc] = exp(-gamma * c_local)
    float ecl[4][2];
#pragma unroll
    for (int nt = 0; nt < 4; nt++)
#pragma unroll
        for (int cc = 0; cc < 2; cc++)
            ecl[nt][cc] = expf(-gamma * (float)(n_w * 32 + nt * 8 + gc + cc));

    if (tid < 64) rowAbsS[tid] = 0.f;

    // ---- initial loads: Q (1536 x 16B) + KV tile 0 ----
    {
#pragma unroll
        for (int it = 0; it < 6; it++) {
            const int unit = tid + it * 256;
            const int seg = unit >> 9, rem = unit & 511;
            const int row = rem >> 3,  u   = rem & 7;
            cp_async16(sb + AT_SQ + seg * 8192 + row * 128 + ((u ^ (row & 7)) * 16),
                       g_q2 + ((size_t)bh * T_ + t0 + row) * 192 + seg * 64 + u * 8);
        }
    }
    auto issueKV = [&](int kt, int st) {
        const int s0 = kt * 64;
#pragma unroll
        for (int it = 0; it < 6; it++) {                 // K: 1536 units
            const int unit = tid + it * 256;
            const int seg = unit >> 9, rem = unit & 511;
            const int row = rem >> 3,  u   = rem & 7;
            cp_async16(sb + AT_SK + st * 24576 + seg * 8192 + row * 128 + ((u ^ (row & 7)) * 16),
                       g_k2 + ((size_t)bh * T_ + s0 + row) * 192 + seg * 64 + u * 8);
        }
#pragma unroll
        for (int it = 0; it < 12; it++) {                // V^T: 3072 units
            const int unit = tid + it * 256;
            const int seg = unit >> 10, rem = unit & 1023;
            const int row = rem >> 3,   u   = rem & 7;
            cp_async16(sb + AT_SV + st * 49152 + seg * 16384 + row * 128 + ((u ^ (row & 7)) * 16),
                       g_vt2 + ((size_t)bh * 128 + row) * 6144 + seg * 2048 + s0 + u * 8);
        }
        cp_commit();
    };
    issueKV(0, 0);

    float vacc[8][4];
#pragma unroll
    for (int i = 0; i < 8; i++)
#pragma unroll
        for (int r = 0; r < 4; r++) vacc[i][r] = 0.f;

    for (int kt = 0; kt <= qi; kt++) {
        const int s0 = kt * 64;
        const int st = kt & 1;
        if (kt < qi) { issueKV(kt + 1, (kt + 1) & 1); cp_wait<1>(); }
        else         { cp_wait<0>(); }
        __syncthreads();

        // ---- QK^T ----
        float sacc[4][4];
#pragma unroll
        for (int i = 0; i < 4; i++)
#pragma unroll
            for (int r = 0; r < 4; r++) sacc[i][r] = 0.f;

#pragma unroll
        for (int c = 0; c < 3; c++) {
            const uint32_t aB = sb + AT_SQ + c * 8192;
            const uint32_t bB = sb + AT_SK + st * 24576 + c * 8192;
#pragma unroll
            for (int ks = 0; ks < 4; ks++) {
                uint32_t af[4];
                {
                    const int row = m_w * 16 + (q & 1) * 8 + l7;
                    const int su  = (ks * 2 + (q >> 1)) ^ (row & 7);
                    ldmatrix_x4(af, aB + row * 128 + su * 16);
                }
                uint32_t bf[2][4];
#pragma unroll
                for (int np = 0; np < 2; np++) {
                    const int row = n_w * 32 + np * 16 + (q >> 1) * 8 + l7;
                    const int su  = (ks * 2 + (q & 1)) ^ (row & 7);
                    ldmatrix_x4(bf[np], bB + row * 128 + su * 16);
                }
#pragma unroll
                for (int nt = 0; nt < 4; nt++)
                    mma16816(sacc[nt], af,
                             bf[nt >> 1][(nt & 1) * 2], bf[nt >> 1][(nt & 1) * 2 + 1]);
            }
        }

        // ---- mask/decay, rowAbs, convert -> S2s ----
        const float e_ts = expf(gamma * (float)(t0 - s0));
        const bool diag = (s0 == t0);
        float pa[2] = {0.f, 0.f};
#pragma unroll
        for (int nt = 0; nt < 4; nt++) {
#pragma unroll
            for (int hrow = 0; hrow < 2; hrow++) {
                const int rl = r0 + hrow * 8;
                uint16_t hi[2], lo[2];
#pragma unroll
                for (int cc = 0; cc < 2; cc++) {
                    const int cl = n_w * 32 + nt * 8 + gc + cc;
                    float v = sacc[nt][hrow * 2 + cc] * rowfac[hrow] * (e_ts * ecl[nt][cc]);
                    if (diag && cl > rl) v = 0.f;
                    pa[hrow] += fabsf(v);
                    hi[cc] = f2bf(v);
                    lo[cc] = f2bf(v - bf2f(hi[cc]));
                }
                const int cl0 = n_w * 32 + nt * 8 + gc;
                const uint32_t hp = (uint32_t)hi[0] | ((uint32_t)hi[1] << 16);
                const uint32_t lp = (uint32_t)lo[0] | ((uint32_t)lo[1] << 16);
                const uint32_t byo = rl * 128 + (((cl0 >> 3) ^ (rl & 7)) * 16) + (cl0 & 7) * 2;
                *(uint32_t*)(smx + AT_SS + byo)            = hp;
                *(uint32_t*)(smx + AT_SS + 8192 + byo)     = hp;
                *(uint32_t*)(smx + AT_SS + 16384 + byo)    = lp;
            }
        }
        // reduce |S| over the 8 cols held by the quad
        pa[0] += __shfl_xor_sync(0xffffffffu, pa[0], 1);
        pa[0] += __shfl_xor_sync(0xffffffffu, pa[0], 2);
        pa[1] += __shfl_xor_sync(0xffffffffu, pa[1], 1);
        pa[1] += __shfl_xor_sync(0xffffffffu, pa[1], 2);
        if ((lid & 3) == 0) {
            atomicAdd(&rowAbsS[r0], pa[0]);
            atomicAdd(&rowAbsS[r1], pa[1]);
        }
        __syncthreads();

        // ---- S @ V ----
#pragma unroll
        for (int c = 0; c < 3; c++) {
            const uint32_t aB = sb + AT_SS + c * 8192;
            const uint32_t bB = sb + AT_SV + st * 49152 + c * 16384;
#pragma unroll
            for (int ks = 0; ks < 4; ks++) {
                uint32_t af[4];
                {
                    const int row = m_w * 16 + (q & 1) * 8 + l7;
                    const int su  = (ks * 2 + (q >> 1)) ^ (row & 7);
                    ldmatrix_x4(af, aB + row * 128 + su * 16);
                }
                uint32_t bf[4][4];
#pragma unroll
                for (int np = 0; np < 4; np++) {
                    const int row = n_w * 64 + np * 16 + (q >> 1) * 8 + l7;
                    const int su  = (ks * 2 + (q & 1)) ^ (row & 7);
                    ldmatrix_x4(bf[np], bB + row * 128 + su * 16);
                }
#pragma unroll
                for (int nt = 0; nt < 8; nt++)
                    mma16816(vacc[nt], af,
                             bf[nt >> 1][(nt & 1) * 2], bf[nt >> 1][(nt & 1) * 2 + 1]);
            }
        }
        __syncthreads();
    }

    // ---- epilogue: denom -> RMSNorm -> gate -> g_y ----
    const float den0 = fminf(fmaxf(rowAbsS[r0], 1.0f), 50000.0f);
    const float den1 = fminf(fmaxf(rowAbsS[r1], 1.0f), 50000.0f);
    const float inv[2] = {1.0f / den0, 1.0f / den1};

    float ss[2] = {0.f, 0.f};
#pragma unroll
    for (int nt = 0; nt < 8; nt++)
#pragma unroll
        for (int hrow = 0; hrow < 2; hrow++)
#pragma unroll
            for (int cc = 0; cc < 2; cc++) {
                const float o = vacc[nt][hrow * 2 + cc] * inv[hrow];
                ss[hrow] = fmaf(o, o, ss[hrow]);
            }
    ss[0] += __shfl_xor_sync(0xffffffffu, ss[0], 1);
    ss[0] += __shfl_xor_sync(0xffffffffu, ss[0], 2);
    ss[1] += __shfl_xor_sync(0xffffffffu, ss[1], 1);
    ss[1] += __shfl_xor_sync(0xffffffffu, ss[1], 2);
    if ((lid & 3) == 0) {
        rssS[r0 * 2 + n_w] = ss[0];
        rssS[r1 * 2 + n_w] = ss[1];
    }
    __syncthreads();

    float rstd[2];
#pragma unroll
    for (int hrow = 0; hrow < 2; hrow++) {
        const int rl = r0 + hrow * 8;
        rstd[hrow] = rsqrtf((rssS[rl * 2] + rssS[rl * 2 + 1]) * (1.0f / 128.0f)
                            + 1.1920929e-7f);
    }

#pragma unroll
    for (int hrow = 0; hrow < 2; hrow++) {
        const int rl = r0 + hrow * 8;
        const int t  = t0 + rl;
        const size_t rb = ((size_t)(b * T_ + t)) * VBD_ + (size_t)h * VD_;
#pragma unroll
        for (int nt = 0; nt < 8; nt++) {
            const int v = n_w * 64 + nt * 8 + gc;
            const float2 gv = *(const float2*)(g_g + rb + v);
            float2 o;
            o.x = vacc[nt][hrow * 2 + 0] * inv[hrow] * rstd[hrow] * gv.x;
            o.y = vacc[nt][hrow * 2 + 1] * inv[hrow] * rstd[hrow] * gv.y;
            *(float2*)(g_y + rb + v) = o;
        }
    }
}

// ---------------------------------------------------------------------------
// Launch
// ---------------------------------------------------------------------------
extern "C" void kernel_launch(void* const* d_in, const int* in_sizes, int n_in,
                              void* d_out, int out_size)
{
    const float* x    = (const float*)d_in[0];
    const float* W_qk = (const float*)d_in[1];
    const float* b_qk = (const float*)d_in[2];
    const float* W_v  = (const float*)d_in[3];
    const float* b_v  = (const float*)d_in[4];
    const float* W_g  = (const float*)d_in[5];
    const float* b_g  = (const float*)d_in[6];
    const float* W_o  = (const float*)d_in[7];
    const float* b_o  = (const float*)d_in[8];
    float* out = (float*)d_out;

    float *qkb, *vbuf, *gbuf, *ybuf;
    uint16_t *x2, *wqk2, *wv2, *wg2, *wo2, *y2;
    cudaGetSymbolAddress((void**)&qkb,  g_qk);
    cudaGetSymbolAddress((void**)&vbuf, g_v);
    cudaGetSymbolAddress((void**)&gbuf, g_g);
    cudaGetSymbolAddress((void**)&ybuf, g_y);
    cudaGetSymbolAddress((void**)&x2,   g_x2);
    cudaGetSymbolAddress((void**)&wqk2, g_wqk2);
    cudaGetSymbolAddress((void**)&wv2,  g_wv2);
    cudaGetSymbolAddress((void**)&wg2,  g_wg2);
    cudaGetSymbolAddress((void**)&wo2,  g_wo2);
    cudaGetSymbolAddress((void**)&y2,   g_y2);
    cudaFuncSetAttribute(gemm_bf16split,
                         cudaFuncAttributeMaxDynamicSharedMemorySize, GEMM_SMEM_BYTES);
    cudaFuncSetAttribute(retention_attn_mma,
                         cudaFuncAttributeMaxDynamicSharedMemorySize, AT_SMEM);

    // --- split/transpose GEMM operands ---
    {
        split_rows<<<(M_ * (C_ / 4) + 255) / 256, 256>>>(x, x2, M_, C_);
        dim3 bt(32, 8);
        split_transpose<<<dim3(2048 / 32, 1024 / 32), bt>>>(W_qk, wqk2, 1024, 2048);
        split_transpose<<<dim3(2048 / 32, 1024 / 32), bt>>>(W_v,  wv2,  1024, 2048);
        split_transpose<<<dim3(2048 / 32, 1024 / 32), bt>>>(W_g,  wg2,  1024, 2048);
        split_transpose<<<dim3(1024 / 32, 2048 / 32), bt>>>(W_o,  wo2,  2048, 1024);
    }

    // --- projection GEMMs (bf16x3, K2 = 3072) ---
    {
        dim3 g(2048 / 128, M_ / 128);
        gemm_bf16split<<<g, 256, GEMM_SMEM_BYTES>>>(x2, wqk2, b_qk, qkb,  3072, 2048);
        gemm_bf16split<<<g, 256, GEMM_SMEM_BYTES>>>(x2, wv2,  b_v,  vbuf, 3072, 2048);
        gemm_bf16split<<<g, 256, GEMM_SMEM_BYTES>>>(x2, wg2,  b_g,  gbuf, 3072, 2048);
    }

    // --- attention operand prep ---
    {
        split_qk_heads<<<(M_ * H_ * 16 + 255) / 256, 256>>>();
        dim3 bt(32, 8);
        transpose_split_v<<<dim3(T_ / 32, VD_ / 32, B_ * H_), bt>>>();
    }

    // --- attention (tensor cores) ---
    {
        dim3 gAttn(T_ / 64, H_, B_);
        retention_attn_mma<<<gAttn, 256, AT_SMEM>>>();
    }

    // --- split y, output GEMM (K2 = 6144) ---
    {
        split_rows<<<(M_ * (VBD_ / 4) + 255) / 256, 256>>>(ybuf, y2, M_, VBD_);
        dim3 g(1024 / 128, M_ / 128);
        gemm_bf16split<<<g, 256, GEMM_SMEM_BYTES>>>(y2, wo2, b_o, out, 6144, 1024);
    }

    (void)in_sizes; (void)n_in; (void)out_size;
}

// round 7
// speedup vs baseline: 2.9536x; 1.0531x over previous
#include <cuda_runtime.h>
#include <cuda_bf16.h>
#include <math.h>
#include <stdint.h>

// Problem constants
#define B_   2
#define T_   2048
#define C_   1024
#define H_   16
#define KD_  64
#define VD_  128
#define VBD_ 2048
#define M_   (B_ * T_)   // 4096 rows

// ---------------------------------------------------------------------------
// Scratch (static device globals -- no allocation allowed)
// ---------------------------------------------------------------------------
__device__ float g_qk[(size_t)M_ * 2048];   // [B*T, 2C]  q | k   (fp32)
__device__ float g_v [(size_t)M_ * 2048];   // [B*T, VBD]         (fp32)
__device__ float g_g [(size_t)M_ * 2048];   // [B*T, VBD] gate    (fp32)

// bf16 [hi|lo] buffers (2 physical segments; 3-term mapping done in mainloops)
__device__ uint16_t g_x2  [(size_t)M_   * 2048];  // x     [4096, 2*1024]
__device__ uint16_t g_wqk2[(size_t)2048 * 2048];  // W_qk^T[2048, 2*1024]
__device__ uint16_t g_wv2 [(size_t)2048 * 2048];  // W_v^T
__device__ uint16_t g_wg2 [(size_t)2048 * 2048];  // W_g^T
__device__ uint16_t g_wo2 [(size_t)1024 * 4096];  // W_o^T [1024, 2*2048]
__device__ uint16_t g_y2  [(size_t)M_   * 4096];  // y     [4096, 2*2048] (attn writes)

// attention operands (head-major, [hi|lo])
__device__ uint16_t g_q2 [(size_t)B_ * H_ * T_ * 128];   // [bh, t, 2*64]
__device__ uint16_t g_k2 [(size_t)B_ * H_ * T_ * 128];   // [bh, t, 2*64]
__device__ uint16_t g_vt2[(size_t)B_ * H_ * VD_ * 4096]; // [bh, v, 2*2048] over s

// ---------------------------------------------------------------------------
// bf16 split helpers
// ---------------------------------------------------------------------------
__device__ __forceinline__ uint16_t f2bf(float x) {
    __nv_bfloat16 h = __float2bfloat16_rn(x);
    return *reinterpret_cast<uint16_t*>(&h);
}
__device__ __forceinline__ float bf2f(uint16_t u) {
    __nv_bfloat16 h = *reinterpret_cast<__nv_bfloat16*>(&u);
    return __bfloat162float(h);
}

// ---------------------------------------------------------------------------
// split_rows: fp32 [R,K] -> bf16 [R,2K] = [hi | lo]
// ---------------------------------------------------------------------------
__global__ void __launch_bounds__(256)
split_rows(const float* __restrict__ in, uint16_t* __restrict__ out, int R, int K)
{
    const int q4 = K >> 2;
    int i = blockIdx.x * blockDim.x + threadIdx.x;
    if (i >= R * q4) return;
    const int m = i / q4, q = i % q4;
    float4 v = *(const float4*)(in + (size_t)m * K + q * 4);
    ushort4 hi, lo;
    hi.x = f2bf(v.x); lo.x = f2bf(v.x - bf2f(hi.x));
    hi.y = f2bf(v.y); lo.y = f2bf(v.y - bf2f(hi.y));
    hi.z = f2bf(v.z); lo.z = f2bf(v.z - bf2f(hi.z));
    hi.w = f2bf(v.w); lo.w = f2bf(v.w - bf2f(hi.w));
    uint16_t* o = out + (size_t)m * 2 * K + q * 4;
    *(ushort4*)(o)     = hi;
    *(ushort4*)(o + K) = lo;
}

// ---------------------------------------------------------------------------
// split_transpose: fp32 W[K,N] -> bf16 out[N,2K] = [hi | lo]
// ---------------------------------------------------------------------------
__global__ void __launch_bounds__(256)
split_transpose(const float* __restrict__ W, uint16_t* __restrict__ out, int K, int N)
{
    __shared__ float t[32][33];
    const int tx = threadIdx.x, ty = threadIdx.y;
    const int n0 = blockIdx.x * 32, k0 = blockIdx.y * 32;
#pragma unroll
    for (int j = 0; j < 4; j++)
        t[ty + j * 8][tx] = W[(size_t)(k0 + ty + j * 8) * N + n0 + tx];
    __syncthreads();
#pragma unroll
    for (int j = 0; j < 4; j++) {
        const int n = n0 + ty + j * 8;
        const float v = t[tx][ty + j * 8];
        const uint16_t hi = f2bf(v);
        const uint16_t lo = f2bf(v - bf2f(hi));
        uint16_t* o = out + (size_t)n * 2 * K + k0 + tx;
        o[0] = hi;
        o[K] = lo;
    }
}

// ---------------------------------------------------------------------------
// split_qk_heads: g_qk [B*T, 2048] -> g_q2/g_k2 [bh, t, 128] ([hi|lo])
// ---------------------------------------------------------------------------
__global__ void __launch_bounds__(256)
split_qk_heads()
{
    int i = blockIdx.x * blockDim.x + threadIdx.x;    // 0 .. M_*H_*16-1
    if (i >= M_ * H_ * 16) return;
    const int d4 = i & 15;
    const int h  = (i >> 4) & 15;
    const int bt = i >> 8;
    const int b  = bt >> 11;
    const int t  = bt & 2047;
    const size_t base = (size_t)bt * 2048 + h * 64 + d4 * 4;
    float4 qv = *(const float4*)(g_qk + base);
    float4 kv = *(const float4*)(g_qk + base + 1024);

    ushort4 qh, ql, kh, kl;
    qh.x = f2bf(qv.x); ql.x = f2bf(qv.x - bf2f(qh.x));
    qh.y = f2bf(qv.y); ql.y = f2bf(qv.y - bf2f(qh.y));
    qh.z = f2bf(qv.z); ql.z = f2bf(qv.z - bf2f(qh.z));
    qh.w = f2bf(qv.w); ql.w = f2bf(qv.w - bf2f(qh.w));
    kh.x = f2bf(kv.x); kl.x = f2bf(kv.x - bf2f(kh.x));
    kh.y = f2bf(kv.y); kl.y = f2bf(kv.y - bf2f(kh.y));
    kh.z = f2bf(kv.z); kl.z = f2bf(kv.z - bf2f(kh.z));
    kh.w = f2bf(kv.w); kl.w = f2bf(kv.w - bf2f(kh.w));

    const size_t ob = ((size_t)(b * H_ + h) * T_ + t) * 128 + d4 * 4;
    *(ushort4*)(g_q2 + ob)      = qh;
    *(ushort4*)(g_q2 + ob + 64) = ql;
    *(ushort4*)(g_k2 + ob)      = kh;
    *(ushort4*)(g_k2 + ob + 64) = kl;
}

// ---------------------------------------------------------------------------
// transpose_split_v: g_v [B*T, 2048] -> g_vt2 [bh, v, 2*2048] ([hi|lo] over s)
// grid (T/32, VD/32, B*H), block (32,8)
// ---------------------------------------------------------------------------
__global__ void __launch_bounds__(256)
transpose_split_v()
{
    __shared__ float t[32][33];
    const int tx = threadIdx.x, ty = threadIdx.y;
    const int s0 = blockIdx.x * 32;
    const int v0 = blockIdx.y * 32;
    const int bh = blockIdx.z;
    const int b  = bh >> 4;
    const int h  = bh & 15;
#pragma unroll
    for (int j = 0; j < 4; j++)
        t[ty + j * 8][tx] = g_v[(size_t)(b * T_ + s0 + ty + j * 8) * 2048 + h * 128 + v0 + tx];
    __syncthreads();
#pragma unroll
    for (int j = 0; j < 4; j++) {
        const int v = v0 + ty + j * 8;
        const float x = t[tx][ty + j * 8];
        const uint16_t hi = f2bf(x);
        const uint16_t lo = f2bf(x - bf2f(hi));
        uint16_t* o = g_vt2 + ((size_t)bh * 128 + v) * 4096 + s0 + tx;
        o[0]    = hi;
        o[2048] = lo;
    }
}

// ---------------------------------------------------------------------------
// Baseline-ISA tensor core helpers
// ---------------------------------------------------------------------------
__device__ __forceinline__ uint32_t smem_u32(const void* p) {
    uint32_t a;
    asm("{ .reg .u64 t; cvta.to.shared.u64 t, %1; cvt.u32.u64 %0, t; }" : "=r"(a) : "l"(p));
    return a;
}
__device__ __forceinline__ void cp_async16(uint32_t dst, const void* src) {
    asm volatile("cp.async.cg.shared.global [%0], [%1], 16;" :: "r"(dst), "l"(src));
}
__device__ __forceinline__ void cp_commit() {
    asm volatile("cp.async.commit_group;" ::: "memory");
}
template <int N>
__device__ __forceinline__ void cp_wait() {
    asm volatile("cp.async.wait_group %0;" :: "n"(N) : "memory");
}
__device__ __forceinline__ void ldmatrix_x4(uint32_t* r, uint32_t addr) {
    asm volatile("ldmatrix.sync.aligned.m8n8.x4.shared.b16 {%0,%1,%2,%3}, [%4];"
                 : "=r"(r[0]), "=r"(r[1]), "=r"(r[2]), "=r"(r[3]) : "r"(addr));
}
__device__ __forceinline__ void mma16816(float* d, const uint32_t* a, uint32_t b0, uint32_t b1) {
    asm volatile(
        "mma.sync.aligned.m16n8k16.row.col.f32.bf16.bf16.f32 "
        "{%0,%1,%2,%3}, {%4,%5,%6,%7}, {%8,%9}, {%0,%1,%2,%3};"
        : "+f"(d[0]), "+f"(d[1]), "+f"(d[2]), "+f"(d[3])
        : "r"(a[0]), "r"(a[1]), "r"(a[2]), "r"(a[3]), "r"(b0), "r"(b1));
}

// ---------------------------------------------------------------------------
// mma.sync bf16x3 GEMM over [hi|lo] storage:
//   virtual chunk c of 3*K/64: A-seg map (hi,hi,lo), B-seg map (hi,lo,hi)
// CTA 128x128, 8 warps, warp tile 64x32, BK=64, 3-stage cp.async pipeline.
// grid = (N/128, M/128), 256 threads.  A2 [M,2K], B2 [N,2K].
// ---------------------------------------------------------------------------
#define GEMM_SMEM_BYTES (3 * 2 * 16384)   // 3 stages x (A 16K + B 16K) = 96 KB

__global__ void __launch_bounds__(256)
gemm_bf16split(const uint16_t* __restrict__ A2, const uint16_t* __restrict__ B2,
               const float* __restrict__ bias, float* __restrict__ Cm,
               int K, int N)
{
    extern __shared__ __align__(128) char smx[];
    const uint32_t sb = smem_u32(smx);

    const int tid = threadIdx.x;
    const int wid = tid >> 5;
    const int lid = tid & 31;
    const int m0 = blockIdx.y * 128;
    const int n0 = blockIdx.x * 128;
    const int wm = (wid & 1) * 64;
    const int wn = (wid >> 1) * 32;
    const int KC = K >> 6;               // chunks per segment
    const int NC = 3 * KC;
    const int K2 = 2 * K;                // physical row stride

    float acc[4][4][4];
#pragma unroll
    for (int i = 0; i < 4; i++)
#pragma unroll
        for (int j = 0; j < 4; j++)
#pragma unroll
            for (int r = 0; r < 4; r++) acc[i][j][r] = 0.f;

    auto issue = [&](int c, int s) {
        const int kseg = (c >= 2 * KC) ? 2 : (c >= KC ? 1 : 0);
        const int kin  = c - kseg * KC;
        const int aCol = ((kseg == 2) ? K : 0) + kin * 64;
        const int bCol = ((kseg == 1) ? K : 0) + kin * 64;
        const uint32_t stA = sb + s * 32768;
        const uint32_t stB = stA + 16384;
#pragma unroll
        for (int it = 0; it < 4; it++) {
            const int unit = tid + it * 256;
            const int row  = unit >> 3;
            const int u    = unit & 7;
            const uint32_t off = row * 128 + ((u ^ (row & 7)) * 16);
            cp_async16(stA + off, A2 + (size_t)(m0 + row) * K2 + aCol + u * 8);
            cp_async16(stB + off, B2 + (size_t)(n0 + row) * K2 + bCol + u * 8);
        }
        cp_commit();
    };

    issue(0, 0);
    issue(1, 1);

    int s = 0;
    for (int c = 0; c < NC; ++c) {
        if (c + 2 < NC)      { issue(c + 2, (c + 2) % 3); cp_wait<2>(); }
        else if (c + 1 < NC) { cp_wait<1>(); }
        else                 { cp_wait<0>(); }
        __syncthreads();

        const uint32_t aB = sb + s * 32768;
        const uint32_t bB = aB + 16384;

#pragma unroll
        for (int ks = 0; ks < 4; ks++) {
            const int q = lid >> 3;
            const int l7 = lid & 7;

            uint32_t af[4][4];
#pragma unroll
            for (int mt = 0; mt < 4; mt++) {
                const int row = wm + mt * 16 + (q & 1) * 8 + l7;
                const int su  = (ks * 2 + (q >> 1)) ^ (row & 7);
                ldmatrix_x4(af[mt], aB + row * 128 + su * 16);
            }
            uint32_t bf[2][4];
#pragma unroll
            for (int np = 0; np < 2; np++) {
                const int row = wn + np * 16 + (q >> 1) * 8 + l7;
                const int su  = (ks * 2 + (q & 1)) ^ (row & 7);
                ldmatrix_x4(bf[np], bB + row * 128 + su * 16);
            }
#pragma unroll
            for (int mt = 0; mt < 4; mt++)
#pragma unroll
                for (int nt = 0; nt < 4; nt++)
                    mma16816(acc[mt][nt], af[mt],
                             bf[nt >> 1][(nt & 1) * 2], bf[nt >> 1][(nt & 1) * 2 + 1]);
        }
        __syncthreads();
        s = (s + 1) % 3;
    }

    const int gr = lid >> 2;
    const int gc = (lid & 3) * 2;
#pragma unroll
    for (int mt = 0; mt < 4; mt++) {
        const int row = m0 + wm + mt * 16 + gr;
#pragma unroll
        for (int nt = 0; nt < 4; nt++) {
            const int col = n0 + wn + nt * 8 + gc;
            const float b0 = __ldg(&bias[col]);
            const float b1 = __ldg(&bias[col + 1]);
            float2 o0, o1;
            o0.x = acc[mt][nt][0] + b0;
            o0.y = acc[mt][nt][1] + b1;
            o1.x = acc[mt][nt][2] + b0;
            o1.y = acc[mt][nt][3] + b1;
            *(float2*)(Cm + (size_t)row * N + col)       = o0;
            *(float2*)(Cm + (size_t)(row + 8) * N + col) = o1;
        }
    }
}

// ---------------------------------------------------------------------------
// mma.sync retention attention ([hi|lo] operands, 3-term virtual loop),
// fused RMSNorm + gating; writes g_y2 ([hi|lo]) directly.
// smem layout (bytes):
//   Q2s @ 0      : 2 segs x (64 x 128B)  = 16384
//   S2s @ 16384  : 2 segs x (64 x 128B)  = 16384
//   K2s @ 32768  : 2 stages x 16384      = 32768
//   Vts @ 65536  : 2 stages x 2 x 16384  = 65536
//   rowAbs @ 131072 (64 f), rss @ 131328 (128 f)
// ---------------------------------------------------------------------------
#define AT_SQ   0
#define AT_SS   16384
#define AT_SK   32768
#define AT_SV   65536
#define AT_RA   131072
#define AT_RS   131328
#define AT_SMEM 131840

__global__ void __launch_bounds__(256)
retention_attn_mma()
{
    extern __shared__ __align__(128) char smx[];
    const uint32_t sb = smem_u32(smx);
    float* rowAbsS = (float*)(smx + AT_RA);
    float* rssS    = (float*)(smx + AT_RS);

    const int tid = threadIdx.x;
    const int wid = tid >> 5;
    const int lid = tid & 31;
    const int q   = lid >> 3;
    const int l7  = lid & 7;
    const int m_w = wid & 3;
    const int n_w = wid >> 2;
    const int gr  = lid >> 2;
    const int gc  = (lid & 3) * 2;

    const int qi = gridDim.x - 1 - blockIdx.x;   // big CTAs first
    const int h  = blockIdx.y;
    const int b  = blockIdx.z;
    const int t0 = qi * 64;
    const int bh = b * H_ + h;

    const float gamma = log1pf(-exp2f(-5.0f - (float)h));
    const float em1g  = expm1f(gamma);

    const int r0 = m_w * 16 + gr;
    const int r1 = r0 + 8;
    float rowfac[2];
#pragma unroll
    for (int hrow = 0; hrow < 2; hrow++) {
        const int rl = r0 + hrow * 8;
        const int t  = t0 + rl;
        const float sc2 = expm1f(gamma * (float)(t + 1)) / em1g;
        rowfac[hrow] = expf(gamma * (float)rl) * rsqrtf(sc2);
    }
    float ecl[4][2];
#pragma unroll
    for (int nt = 0; nt < 4; nt++)
#pragma unroll
        for (int cc = 0; cc < 2; cc++)
            ecl[nt][cc] = expf(-gamma * (float)(n_w * 32 + nt * 8 + gc + cc));

    if (tid < 64) rowAbsS[tid] = 0.f;

    // ---- Q load: 2 segs x 512 units = 1024 ----
    {
#pragma unroll
        for (int it = 0; it < 4; it++) {
            const int unit = tid + it * 256;
            const int seg = unit >> 9, rem = unit & 511;
            const int row = rem >> 3,  u   = rem & 7;
            cp_async16(sb + AT_SQ + seg * 8192 + row * 128 + ((u ^ (row & 7)) * 16),
                       g_q2 + ((size_t)bh * T_ + t0 + row) * 128 + seg * 64 + u * 8);
        }
    }
    auto issueKV = [&](int kt, int st) {
        const int s0 = kt * 64;
#pragma unroll
        for (int it = 0; it < 4; it++) {                 // K: 1024 units
            const int unit = tid + it * 256;
            const int seg = unit >> 9, rem = unit & 511;
            const int row = rem >> 3,  u   = rem & 7;
            cp_async16(sb + AT_SK + st * 16384 + seg * 8192 + row * 128 + ((u ^ (row & 7)) * 16),
                       g_k2 + ((size_t)bh * T_ + s0 + row) * 128 + seg * 64 + u * 8);
        }
#pragma unroll
        for (int it = 0; it < 8; it++) {                 // V^T: 2048 units
            const int unit = tid + it * 256;
            const int seg = unit >> 10, rem = unit & 1023;
            const int row = rem >> 3,   u   = rem & 7;
            cp_async16(sb + AT_SV + st * 32768 + seg * 16384 + row * 128 + ((u ^ (row & 7)) * 16),
                       g_vt2 + ((size_t)bh * 128 + row) * 4096 + seg * 2048 + s0 + u * 8);
        }
        cp_commit();
    };
    issueKV(0, 0);

    float vacc[8][4];
#pragma unroll
    for (int i = 0; i < 8; i++)
#pragma unroll
        for (int r = 0; r < 4; r++) vacc[i][r] = 0.f;

    for (int kt = 0; kt <= qi; kt++) {
        const int s0 = kt * 64;
        const int st = kt & 1;
        if (kt < qi) { issueKV(kt + 1, (kt + 1) & 1); cp_wait<1>(); }
        else         { cp_wait<0>(); }
        __syncthreads();

        // ---- QK^T: c -> (Q seg: hi,hi,lo) x (K seg: hi,lo,hi) ----
        float sacc[4][4];
#pragma unroll
        for (int i = 0; i < 4; i++)
#pragma unroll
            for (int r = 0; r < 4; r++) sacc[i][r] = 0.f;

#pragma unroll
        for (int c = 0; c < 3; c++) {
            const uint32_t aB = sb + AT_SQ + ((c == 2) ? 8192 : 0);
            const uint32_t bB = sb + AT_SK + st * 16384 + ((c == 1) ? 8192 : 0);
#pragma unroll
            for (int ks = 0; ks < 4; ks++) {
                uint32_t af[4];
                {
                    const int row = m_w * 16 + (q & 1) * 8 + l7;
                    const int su  = (ks * 2 + (q >> 1)) ^ (row & 7);
                    ldmatrix_x4(af, aB + row * 128 + su * 16);
                }
                uint32_t bf[2][4];
#pragma unroll
                for (int np = 0; np < 2; np++) {
                    const int row = n_w * 32 + np * 16 + (q >> 1) * 8 + l7;
                    const int su  = (ks * 2 + (q & 1)) ^ (row & 7);
                    ldmatrix_x4(bf[np], bB + row * 128 + su * 16);
                }
#pragma unroll
                for (int nt = 0; nt < 4; nt++)
                    mma16816(sacc[nt], af,
                             bf[nt >> 1][(nt & 1) * 2], bf[nt >> 1][(nt & 1) * 2 + 1]);
            }
        }

        // ---- mask/decay, rowAbs, convert -> S2s [hi|lo] ----
        const float e_ts = expf(gamma * (float)(t0 - s0));
        const bool diag = (s0 == t0);
        float pa[2] = {0.f, 0.f};
#pragma unroll
        for (int nt = 0; nt < 4; nt++) {
#pragma unroll
            for (int hrow = 0; hrow < 2; hrow++) {
                const int rl = r0 + hrow * 8;
                uint16_t hi[2], lo[2];
#pragma unroll
                for (int cc = 0; cc < 2; cc++) {
                    const int cl = n_w * 32 + nt * 8 + gc + cc;
                    float v = sacc[nt][hrow * 2 + cc] * rowfac[hrow] * (e_ts * ecl[nt][cc]);
                    if (diag && cl > rl) v = 0.f;
                    pa[hrow] += fabsf(v);
                    hi[cc] = f2bf(v);
                    lo[cc] = f2bf(v - bf2f(hi[cc]));
                }
                const int cl0 = n_w * 32 + nt * 8 + gc;
                const uint32_t hp = (uint32_t)hi[0] | ((uint32_t)hi[1] << 16);
                const uint32_t lp = (uint32_t)lo[0] | ((uint32_t)lo[1] << 16);
                const uint32_t byo = rl * 128 + (((cl0 >> 3) ^ (rl & 7)) * 16) + (cl0 & 7) * 2;
                *(uint32_t*)(smx + AT_SS + byo)        = hp;
                *(uint32_t*)(smx + AT_SS + 8192 + byo) = lp;
            }
        }
        pa[0] += __shfl_xor_sync(0xffffffffu, pa[0], 1);
        pa[0] += __shfl_xor_sync(0xffffffffu, pa[0], 2);
        pa[1] += __shfl_xor_sync(0xffffffffu, pa[1], 1);
        pa[1] += __shfl_xor_sync(0xffffffffu, pa[1], 2);
        if ((lid & 3) == 0) {
            atomicAdd(&rowAbsS[r0], pa[0]);
            atomicAdd(&rowAbsS[r1], pa[1]);
        }
        __syncthreads();

        // ---- S @ V: c -> (S seg: hi,hi,lo) x (V seg: hi,lo,hi) ----
#pragma unroll
        for (int c = 0; c < 3; c++) {
            const uint32_t aB = sb + AT_SS + ((c == 2) ? 8192 : 0);
            const uint32_t bB = sb + AT_SV + st * 32768 + ((c == 1) ? 16384 : 0);
#pragma unroll
            for (int ks = 0; ks < 4; ks++) {
                uint32_t af[4];
                {
                    const int row = m_w * 16 + (q & 1) * 8 + l7;
                    const int su  = (ks * 2 + (q >> 1)) ^ (row & 7);
                    ldmatrix_x4(af, aB + row * 128 + su * 16);
                }
                uint32_t bf[4][4];
#pragma unroll
                for (int np = 0; np < 4; np++) {
                    const int row = n_w * 64 + np * 16 + (q >> 1) * 8 + l7;
                    const int su  = (ks * 2 + (q & 1)) ^ (row & 7);
                    ldmatrix_x4(bf[np], bB + row * 128 + su * 16);
                }
#pragma unroll
                for (int nt = 0; nt < 8; nt++)
                    mma16816(vacc[nt], af,
                             bf[nt >> 1][(nt & 1) * 2], bf[nt >> 1][(nt & 1) * 2 + 1]);
            }
        }
        __syncthreads();
    }

    // ---- epilogue: denom -> RMSNorm -> gate -> g_y2 ([hi|lo]) ----
    const float den0 = fminf(fmaxf(rowAbsS[r0], 1.0f), 50000.0f);
    const float den1 = fminf(fmaxf(rowAbsS[r1], 1.0f), 50000.0f);
    const float inv[2] = {1.0f / den0, 1.0f / den1};

    float ss[2] = {0.f, 0.f};
#pragma unroll
    for (int nt = 0; nt < 8; nt++)
#pragma unroll
        for (int hrow = 0; hrow < 2; hrow++)
#pragma unroll
            for (int cc = 0; cc < 2; cc++) {
                const float o = vacc[nt][hrow * 2 + cc] * inv[hrow];
                ss[hrow] = fmaf(o, o, ss[hrow]);
            }
    ss[0] += __shfl_xor_sync(0xffffffffu, ss[0], 1);
    ss[0] += __shfl_xor_sync(0xffffffffu, ss[0], 2);
    ss[1] += __shfl_xor_sync(0xffffffffu, ss[1], 1);
    ss[1] += __shfl_xor_sync(0xffffffffu, ss[1], 2);
    if ((lid & 3) == 0) {
        rssS[r0 * 2 + n_w] = ss[0];
        rssS[r1 * 2 + n_w] = ss[1];
    }
    __syncthreads();

    float rstd[2];
#pragma unroll
    for (int hrow = 0; hrow < 2; hrow++) {
        const int rl = r0 + hrow * 8;
        rstd[hrow] = rsqrtf((rssS[rl * 2] + rssS[rl * 2 + 1]) * (1.0f / 128.0f)
                            + 1.1920929e-7f);
    }

#pragma unroll
    for (int hrow = 0; hrow < 2; hrow++) {
        const int rl = r0 + hrow * 8;
        const int t  = t0 + rl;
        const size_t gbase = ((size_t)(b * T_ + t)) * VBD_ + (size_t)h * VD_;
        const size_t ybase = ((size_t)(b * T_ + t)) * 4096 + (size_t)h * VD_;
#pragma unroll
        for (int nt = 0; nt < 8; nt++) {
            const int v = n_w * 64 + nt * 8 + gc;
            const float2 gv = *(const float2*)(g_g + gbase + v);
            float ox = vacc[nt][hrow * 2 + 0] * inv[hrow] * rstd[hrow] * gv.x;
            float oy = vacc[nt][hrow * 2 + 1] * inv[hrow] * rstd[hrow] * gv.y;
            uint16_t hx = f2bf(ox), hy = f2bf(oy);
            uint16_t lx = f2bf(ox - bf2f(hx)), ly = f2bf(oy - bf2f(hy));
            *(uint32_t*)(g_y2 + ybase + v)        = (uint32_t)hx | ((uint32_t)hy << 16);
            *(uint32_t*)(g_y2 + ybase + 2048 + v) = (uint32_t)lx | ((uint32_t)ly << 16);
        }
    }
}

// ---------------------------------------------------------------------------
// Launch
// ---------------------------------------------------------------------------
extern "C" void kernel_launch(void* const* d_in, const int* in_sizes, int n_in,
                              void* d_out, int out_size)
{
    const float* x    = (const float*)d_in[0];
    const float* W_qk = (const float*)d_in[1];
    const float* b_qk = (const float*)d_in[2];
    const float* W_v  = (const float*)d_in[3];
    const float* b_v  = (const float*)d_in[4];
    const float* W_g  = (const float*)d_in[5];
    const float* b_g  = (const float*)d_in[6];
    const float* W_o  = (const float*)d_in[7];
    const float* b_o  = (const float*)d_in[8];
    float* out = (float*)d_out;

    float *qkb, *vbuf, *gbuf;
    uint16_t *x2, *wqk2, *wv2, *wg2, *wo2, *y2;
    cudaGetSymbolAddress((void**)&qkb,  g_qk);
    cudaGetSymbolAddress((void**)&vbuf, g_v);
    cudaGetSymbolAddress((void**)&gbuf, g_g);
    cudaGetSymbolAddress((void**)&x2,   g_x2);
    cudaGetSymbolAddress((void**)&wqk2, g_wqk2);
    cudaGetSymbolAddress((void**)&wv2,  g_wv2);
    cudaGetSymbolAddress((void**)&wg2,  g_wg2);
    cudaGetSymbolAddress((void**)&wo2,  g_wo2);
    cudaGetSymbolAddress((void**)&y2,   g_y2);
    cudaFuncSetAttribute(gemm_bf16split,
                         cudaFuncAttributeMaxDynamicSharedMemorySize, GEMM_SMEM_BYTES);
    cudaFuncSetAttribute(retention_attn_mma,
                         cudaFuncAttributeMaxDynamicSharedMemorySize, AT_SMEM);

    // --- split/transpose GEMM operands ([hi|lo]) ---
    {
        split_rows<<<(M_ * (C_ / 4) + 255) / 256, 256>>>(x, x2, M_, C_);
        dim3 bt(32, 8);
        split_transpose<<<dim3(2048 / 32, 1024 / 32), bt>>>(W_qk, wqk2, 1024, 2048);
        split_transpose<<<dim3(2048 / 32, 1024 / 32), bt>>>(W_v,  wv2,  1024, 2048);
        split_transpose<<<dim3(2048 / 32, 1024 / 32), bt>>>(W_g,  wg2,  1024, 2048);
        split_transpose<<<dim3(1024 / 32, 2048 / 32), bt>>>(W_o,  wo2,  2048, 1024);
    }

    // --- projection GEMMs (K = 1024) ---
    {
        dim3 g(2048 / 128, M_ / 128);
        gemm_bf16split<<<g, 256, GEMM_SMEM_BYTES>>>(x2, wqk2, b_qk, qkb,  1024, 2048);
        gemm_bf16split<<<g, 256, GEMM_SMEM_BYTES>>>(x2, wv2,  b_v,  vbuf, 1024, 2048);
        gemm_bf16split<<<g, 256, GEMM_SMEM_BYTES>>>(x2, wg2,  b_g,  gbuf, 1024, 2048);
    }

    // --- attention operand prep ---
    {
        split_qk_heads<<<(M_ * H_ * 16 + 255) / 256, 256>>>();
        dim3 bt(32, 8);
        transpose_split_v<<<dim3(T_ / 32, VD_ / 32, B_ * H_), bt>>>();
    }

    // --- attention (tensor cores; writes g_y2 directly) ---
    {
        dim3 gAttn(T_ / 64, H_, B_);
        retention_attn_mma<<<gAttn, 256, AT_SMEM>>>();
    }

    // --- output GEMM (K = 2048) ---
    {
        dim3 g(1024 / 128, M_ / 128);
        gemm_bf16split<<<g, 256, GEMM_SMEM_BYTES>>>(y2, wo2, b_o, out, 2048, 1024);
    }

    (void)in_sizes; (void)n_in; (void)out_size;
}